// round 14
// baseline (speedup 1.0000x reference)
#include <cuda_runtime.h>
#include <cuda_fp16.h>

#define EPB 128

#define INV4        0.25f
#define INV_SQRT10  0.3162277660168379f
#define INV8        0.125f
#define INV_SQRT32  0.1767766952966369f
#define INV_SQRT48  0.1443375672974064f
#define INV_SQRT3   0.5773502691896258f
#define C_S         0.3826834323650898f
#define C_X         0.9238795325112867f

#define N_NODES_MAX 100000
#define SOS 132   // sOUT padded stride

// XOR swizzle for sOUT column reads (R8, proven)
#define SWX(r)      (8 * (((r) >> 3) & 3))
#define SWIZ(r, c)  ((r) * SOS + ((c) ^ SWX(r)))

typedef unsigned long long U64;

// ---------------------------------------------------------------------------
// Scratch
// ---------------------------------------------------------------------------
__device__ __align__(16) float g_sscal[(size_t)N_NODES_MAX * 48];
__device__ __align__(16) float g_x1  [(size_t)N_NODES_MAX * 16];
__device__ __align__(16) float g_mid [(size_t)N_NODES_MAX * 64];
__device__ __align__(16) float g_s2  [(size_t)N_NODES_MAX];
__device__ __align__(16) float g_h0  [(size_t)N_NODES_MAX * 32];
__device__ __align__(16) float g_hv  [(size_t)N_NODES_MAX * 48];
__device__ __align__(16) float g_mid2[(size_t)N_NODES_MAX * 48];

__device__ __forceinline__ float fast_sigmoid(float x) {
    return __fdividef(1.0f, 1.0f + __expf(-x));
}
__device__ __forceinline__ float fast_silu(float x) {
    return __fdividef(x, 1.0f + __expf(-x));
}

__device__ __forceinline__ U64 pack2(float a, float b) {
    U64 r; asm("mov.b64 %0, {%1, %2};" : "=l"(r) : "f"(a), "f"(b)); return r;
}
__device__ __forceinline__ float2 unpk2(U64 v) {
    float2 r; asm("mov.b64 {%0, %1}, %2;" : "=f"(r.x), "=f"(r.y) : "l"(v)); return r;
}
__device__ __forceinline__ void fma2(U64& d, U64 a, U64 b) {
    asm("fma.rn.f32x2 %0, %1, %2, %0;" : "+l"(d) : "l"(a), "l"(b));
}
__device__ __forceinline__ void mul2(U64& d, U64 a) {
    asm("mul.rn.f32x2 %0, %0, %1;" : "+l"(d) : "l"(a));
}
__device__ __forceinline__ void red4(float* addr, float a, float b, float c, float d) {
    asm volatile("red.global.add.v4.f32 [%0], {%1, %2, %3, %4};"
                 :: "l"(addr), "f"(a), "f"(b), "f"(c), "f"(d) : "memory");
}
__device__ __forceinline__ unsigned h2bits(float a, float b) {
    __half2 h = __floats2half2_rn(a, b);
    return *(unsigned*)&h;
}
__device__ __forceinline__ float2 h2f2(unsigned u) {
    __half2 h = *(__half2*)&u;
    return __half22float2(h);
}

// ---------------------------------------------------------------------------
// Kernel A: per-node precompute  s_scal[N,48], x1[N,16]; zero mid & mid2
// ---------------------------------------------------------------------------
__global__ __launch_bounds__(128)
void k_node1(const float* __restrict__ ni, const float* __restrict__ na,
             const float* __restrict__ Wsc1, const float* __restrict__ Wl11, int N)
{
    __shared__ __align__(16) float sA[16 * 48];
    __shared__ __align__(16) float sB[16 * 16];
    for (int i = threadIdx.x; i < 16 * 48; i += 128) sA[i] = Wsc1[i];
    for (int i = threadIdx.x; i < 16 * 16; i += 128) sB[i] = Wl11[i];
    __syncthreads();

    int n = blockIdx.x * 128 + threadIdx.x;
    if (n >= N) return;

    float in[16];
    const float4* p = (const float4*)(ni + (size_t)n * 16);
#pragma unroll
    for (int i = 0; i < 4; i++) {
        float4 t = p[i];
        in[4 * i] = t.x; in[4 * i + 1] = t.y; in[4 * i + 2] = t.z; in[4 * i + 3] = t.w;
    }
    float a = na[n];

    U64 sc2[24], xv2[8];
#pragma unroll
    for (int c = 0; c < 24; c++) sc2[c] = 0ull;
#pragma unroll
    for (int j = 0; j < 8; j++) xv2[j] = 0ull;

#pragma unroll
    for (int k = 0; k < 16; k++) {
        U64 xx = pack2(in[k], in[k]);
        const ulonglong2* wa = (const ulonglong2*)(sA + k * 48);
#pragma unroll
        for (int c4 = 0; c4 < 12; c4++) {
            ulonglong2 w = wa[c4];
            fma2(sc2[2 * c4], w.x, xx);
            fma2(sc2[2 * c4 + 1], w.y, xx);
        }
        const ulonglong2* wb = (const ulonglong2*)(sB + k * 16);
#pragma unroll
        for (int j4 = 0; j4 < 4; j4++) {
            ulonglong2 w = wb[j4];
            fma2(xv2[2 * j4], w.x, xx);
            fma2(xv2[2 * j4 + 1], w.y, xx);
        }
    }

    float sa = INV4 * a;
    float* sd = g_sscal + (size_t)n * 48;
#pragma unroll
    for (int c = 0; c < 24; c++) {
        float2 t = unpk2(sc2[c]);
        sd[2 * c] = t.x * sa; sd[2 * c + 1] = t.y * sa;
    }
    float* xd = g_x1 + (size_t)n * 16;
#pragma unroll
    for (int j = 0; j < 8; j++) {
        float2 t = unpk2(xv2[j]);
        xd[2 * j] = t.x * sa; xd[2 * j + 1] = t.y * sa;
    }

    float4 z = make_float4(0.f, 0.f, 0.f, 0.f);
    float4* mz = (float4*)(g_mid + (size_t)n * 64);
#pragma unroll
    for (int i = 0; i < 16; i++) mz[i] = z;
    float4* mz2 = (float4*)(g_mid2 + (size_t)n * 48);
#pragma unroll
    for (int i = 0; i < 12; i++) mz2[i] = z;
}

// ---------------------------------------------------------------------------
// Kernel B: edge pass 1 (fp16 smem H, coalesced elen, 6 blocks/SM)
// sU[2048]: {W1[640] | sEL[1280]@640} -> W2[2048]
// sBUF[4224]: elen-linear stage -> H fp16 [64][128] -> sOUT fp32 [32][SOS]
// ---------------------------------------------------------------------------
__global__ __launch_bounds__(128, 6)
void k_edge1(const float* __restrict__ elen, const float* __restrict__ eattr,
             const int* __restrict__ esrc, const int* __restrict__ edst,
             const float* __restrict__ W1, const float* __restrict__ W2, int E)
{
    __shared__ __align__(16) float sU[2048];
    __shared__ __align__(16) float sBUF[32 * SOS];

    float* sEL = sU + 640;
    __half* sHh = (__half*)sBUF;
    float* sOUT = sBUF;

    int t = threadIdx.x;
    int warp = t >> 5, lane = t & 31;
    int colb = 4 * lane;
    int hb = warp * 16;
    int ob = warp * 8;
    int j = lane & 3;
    int g = lane >> 2;

    for (int i = t; i < 640; i += 128) sU[i] = W1[i];

    int blockBase = blockIdx.x * EPB;
    int e = blockBase + t;
    int eL = e < E ? e : E - 1;

    int srcIdx = esrc[eL];
    int dstIdx = edst[eL];
    float4 ea = ((const float4*)eattr)[eL];

    // coalesced elen staging: slab -> sBUF(linear) -> sEL(transposed)
    {
        int gbase = blockBase * 10;
        int lim = E * 10;
#pragma unroll
        for (int i = 0; i < 10; i++) {
            int gi = gbase + i * 128 + t;
            sBUF[i * 128 + t] = (gi < lim) ? elen[gi] : 0.f;
        }
        __syncthreads();
        const float2* rp = (const float2*)(sBUF + t * 10);
        float el[10];
#pragma unroll
        for (int i = 0; i < 5; i++) {
            float2 v = rp[i];
            el[2 * i] = v.x; el[2 * i + 1] = v.y;
        }
        __syncthreads();
#pragma unroll
        for (int i = 0; i < 10; i++) sEL[i * 128 + t] = el[i];
    }
    __syncthreads();

    // ---- layer1 in two halves of 8 hidden; store H as fp16
#pragma unroll
    for (int half = 0; half < 2; half++) {
        int hbh = hb + 8 * half;
        U64 hacc[4][4];
#pragma unroll
        for (int a = 0; a < 4; a++)
#pragma unroll
            for (int b = 0; b < 4; b++) hacc[a][b] = 0ull;

#pragma unroll
        for (int k = 0; k < 10; k++) {
            float4 x4 = *(const float4*)(sEL + k * 128 + colb);
            const ulonglong2* wp = (const ulonglong2*)(sU + k * 64 + hbh);
            ulonglong2 w0 = wp[0], w1 = wp[1];
            float xs4[4] = { x4.x, x4.y, x4.z, x4.w };
#pragma unroll
            for (int ei = 0; ei < 4; ei++) {
                U64 xx = pack2(xs4[ei], xs4[ei]);
                fma2(hacc[ei][0], w0.x, xx); fma2(hacc[ei][1], w0.y, xx);
                fma2(hacc[ei][2], w1.x, xx); fma2(hacc[ei][3], w1.y, xx);
            }
        }
#pragma unroll
        for (int jp = 0; jp < 4; jp++) {
            float2 f[4];
#pragma unroll
            for (int ei = 0; ei < 4; ei++) {
                f[ei] = unpk2(hacc[ei][jp]);
                f[ei].x = fast_silu(f[ei].x * INV_SQRT10);
                f[ei].y = fast_silu(f[ei].y * INV_SQRT10);
            }
            *(uint2*)(sHh + (hbh + 2 * jp) * 128 + colb) =
                make_uint2(h2bits(f[0].x, f[1].x), h2bits(f[2].x, f[3].x));
            *(uint2*)(sHh + (hbh + 2 * jp + 1) * 128 + colb) =
                make_uint2(h2bits(f[0].y, f[1].y), h2bits(f[2].y, f[3].y));
        }
    }
    __syncthreads();

    for (int i = t; i < 2048; i += 128) sU[i] = W2[i];
    __syncthreads();

    // ---- layer2: thread tile = 4 edges x 8 outs
    U64 acc[4][4];
#pragma unroll
    for (int a = 0; a < 4; a++)
#pragma unroll
        for (int b = 0; b < 4; b++) acc[a][b] = 0ull;

#pragma unroll 8
    for (int k = 0; k < 64; k++) {
        uint2 hr = *(const uint2*)(sHh + k * 128 + colb);
        float2 fa = h2f2(hr.x), fb = h2f2(hr.y);
        const ulonglong2* wp = (const ulonglong2*)(sU + k * 32 + ob);
        ulonglong2 wa = wp[0], wb = wp[1];
        float hs[4] = { fa.x, fa.y, fb.x, fb.y };
#pragma unroll
        for (int ei = 0; ei < 4; ei++) {
            U64 xx = pack2(hs[ei], hs[ei]);
            fma2(acc[ei][0], wa.x, xx); fma2(acc[ei][1], wa.y, xx);
            fma2(acc[ei][2], wb.x, xx); fma2(acc[ei][3], wb.y, xx);
        }
    }
    __syncthreads();   // H reads done; overwrite as sOUT

#pragma unroll
    for (int op = 0; op < 4; op++) {
        float2 f[4];
#pragma unroll
        for (int ei = 0; ei < 4; ei++) f[ei] = unpk2(acc[ei][op]);
        int r0 = ob + 2 * op, r1 = ob + 2 * op + 1;
        *(float4*)(sOUT + SWIZ(r0, colb)) =
            make_float4(f[0].x * INV8, f[1].x * INV8, f[2].x * INV8, f[3].x * INV8);
        *(float4*)(sOUT + SWIZ(r1, colb)) =
            make_float4(f[0].y * INV8, f[1].y * INV8, f[2].y * INV8, f[3].y * INV8);
    }
    __syncthreads();

#pragma unroll
    for (int p = 0; p < 4; p++) {
        int q = 8 * p + g;
        int eQ = blockBase + 32 * warp + q;
        int sE  = __shfl_sync(0xffffffffu, srcIdx, q);
        int dE  = __shfl_sync(0xffffffffu, dstIdx, q);
        float eax = __shfl_sync(0xffffffffu, ea.x, q);
        float eay = __shfl_sync(0xffffffffu, ea.y, q);
        float eaz = __shfl_sync(0xffffffffu, ea.z, q);
        float eaw = __shfl_sync(0xffffffffu, ea.w, q);
        if (eQ < E) {
            int col = 32 * warp + q;
            float4 x = *(const float4*)(g_x1 + (size_t)sE * 16 + 4 * j);
            float* mrow = g_mid + (size_t)dE * 64;
            float w0 = sOUT[SWIZ(4 * j + 0, col)];
            float w1 = sOUT[SWIZ(4 * j + 1, col)];
            float w2 = sOUT[SWIZ(4 * j + 2, col)];
            float w3 = sOUT[SWIZ(4 * j + 3, col)];
            red4(mrow + 4 * j, x.x * eax * w0, x.y * eax * w1,
                               x.z * eax * w2, x.w * eax * w3);
            float t0 = x.x * sOUT[SWIZ(16 + 4 * j + 0, col)];
            float t1 = x.y * sOUT[SWIZ(16 + 4 * j + 1, col)];
            float t2 = x.z * sOUT[SWIZ(16 + 4 * j + 2, col)];
            float t3 = x.w * sOUT[SWIZ(16 + 4 * j + 3, col)];
            float* f1p = mrow + 16 + 12 * j;
            red4(f1p + 0, t0 * eay, t0 * eaz, t0 * eaw, t1 * eay);
            red4(f1p + 4, t1 * eaz, t1 * eaw, t2 * eay, t2 * eaz);
            red4(f1p + 8, t2 * eaw, t3 * eay, t3 * eaz, t3 * eaw);
        }
    }
}

// ---------------------------------------------------------------------------
// Kernel C: per-node mid processing (R12 staged/SoA, fp32 h0/hv)
// ---------------------------------------------------------------------------
__global__ __launch_bounds__(128)
void k_node2(const float* __restrict__ na,
             const float* __restrict__ Wl2s, const float* __restrict__ Wl2v,
             const float* __restrict__ Wsc2, const float* __restrict__ W12s,
             const float* __restrict__ W12v, int N)
{
    __shared__ __align__(16) float sL2S[16 * 48];
    __shared__ __align__(16) float sL2V[16 * 16];
    __shared__ float sSC2[32];
    __shared__ __align__(16) float s12S[32 * 32];
    __shared__ __align__(16) float s12V[16 * 16];
    for (int i = threadIdx.x; i < 16 * 48; i += 128) sL2S[i] = Wl2s[i];
    for (int i = threadIdx.x; i < 16 * 16; i += 128) sL2V[i] = Wl2v[i];
    for (int i = threadIdx.x; i < 32;      i += 128) sSC2[i] = Wsc2[i];
    for (int i = threadIdx.x; i < 32 * 32; i += 128) s12S[i] = W12s[i];
    for (int i = threadIdx.x; i < 16 * 16; i += 128) s12V[i] = W12v[i];
    __syncthreads();

    int n = blockIdx.x * 128 + threadIdx.x;
    if (n >= N) return;

    float a = na[n];
    const float4* mp = (const float4*)(g_mid + (size_t)n * 64);

    float m0[16];
#pragma unroll
    for (int i = 0; i < 4; i++) {
        float4 t = mp[i];
        m0[4 * i] = t.x * INV4; m0[4 * i + 1] = t.y * INV4;
        m0[4 * i + 2] = t.z * INV4; m0[4 * i + 3] = t.w * INV4;
    }
    U64 ys2[24];
#pragma unroll
    for (int c = 0; c < 24; c++) ys2[c] = 0ull;
#pragma unroll
    for (int u = 0; u < 16; u++) {
        U64 xx = pack2(m0[u], m0[u]);
        const ulonglong2* wr = (const ulonglong2*)(sL2S + u * 48);
#pragma unroll
        for (int c4 = 0; c4 < 12; c4++) {
            ulonglong2 w = wr[c4];
            fma2(ys2[2 * c4], w.x, xx);
            fma2(ys2[2 * c4 + 1], w.y, xx);
        }
    }

    const float4* ssp = (const float4*)(g_sscal + (size_t)n * 48);
    float s = INV4 * a;
    float scal[32], gs[16];
#pragma unroll
    for (int i = 0; i < 8; i++) {
        float4 ss = ssp[i];
        float2 y0 = unpk2(ys2[2 * i]);
        float2 y1 = unpk2(ys2[2 * i + 1]);
        scal[4 * i + 0] = fast_silu(C_S * ss.x + C_X * (y0.x * s));
        scal[4 * i + 1] = fast_silu(C_S * ss.y + C_X * (y0.y * s));
        scal[4 * i + 2] = fast_silu(C_S * ss.z + C_X * (y1.x * s));
        scal[4 * i + 3] = fast_silu(C_S * ss.w + C_X * (y1.y * s));
    }
#pragma unroll
    for (int i = 0; i < 4; i++) {
        float4 ss = ssp[8 + i];
        float2 y0 = unpk2(ys2[16 + 2 * i]);
        float2 y1 = unpk2(ys2[16 + 2 * i + 1]);
        gs[4 * i + 0] = fast_sigmoid(C_S * ss.x + C_X * (y0.x * s)) * s;
        gs[4 * i + 1] = fast_sigmoid(C_S * ss.y + C_X * (y0.y * s)) * s;
        gs[4 * i + 2] = fast_sigmoid(C_S * ss.z + C_X * (y1.x * s)) * s;
        gs[4 * i + 3] = fast_sigmoid(C_S * ss.w + C_X * (y1.y * s)) * s;
    }

    float s2v = 0.f;
#pragma unroll
    for (int o = 0; o < 32; o++) s2v += scal[o] * sSC2[o];
    g_s2[n] = s2v * INV_SQRT32 * a;

    U64 h02[16];
#pragma unroll
    for (int p = 0; p < 16; p++) h02[p] = 0ull;
#pragma unroll
    for (int o = 0; o < 32; o++) {
        U64 xx = pack2(scal[o], scal[o]);
        const ulonglong2* wr = (const ulonglong2*)(s12S + o * 32);
#pragma unroll
        for (int p4 = 0; p4 < 8; p4++) {
            ulonglong2 w = wr[p4];
            fma2(h02[2 * p4], w.x, xx);
            fma2(h02[2 * p4 + 1], w.y, xx);
        }
    }
    float sh = INV_SQRT32 * a;
    float* h0d = g_h0 + (size_t)n * 32;
#pragma unroll
    for (int p = 0; p < 16; p++) {
        float2 t2 = unpk2(h02[p]);
        h0d[2 * p] = t2.x * sh; h0d[2 * p + 1] = t2.y * sh;
    }

    float m1[48];
#pragma unroll
    for (int i = 0; i < 12; i++) {
        float4 t = mp[4 + i];
        m1[4 * i] = t.x * INV4; m1[4 * i + 1] = t.y * INV4;
        m1[4 * i + 2] = t.z * INV4; m1[4 * i + 3] = t.w * INV4;
    }
    U64 yv0[8], yv1[8], yv2[8];
#pragma unroll
    for (int q = 0; q < 8; q++) { yv0[q] = 0ull; yv1[q] = 0ull; yv2[q] = 0ull; }
#pragma unroll
    for (int u = 0; u < 16; u++) {
        U64 p0 = pack2(m1[3 * u + 0], m1[3 * u + 0]);
        U64 p1 = pack2(m1[3 * u + 1], m1[3 * u + 1]);
        U64 p2 = pack2(m1[3 * u + 2], m1[3 * u + 2]);
        const U64* wr = (const U64*)(sL2V + u * 16);
#pragma unroll
        for (int q = 0; q < 8; q++) {
            U64 w = wr[q];
            fma2(yv0[q], w, p0);
            fma2(yv1[q], w, p1);
            fma2(yv2[q], w, p2);
        }
    }
#pragma unroll
    for (int q = 0; q < 8; q++) {
        U64 gp = pack2(gs[2 * q], gs[2 * q + 1]);
        mul2(yv0[q], gp);
        mul2(yv1[q], gp);
        mul2(yv2[q], gp);
    }

    U64 hv0[8], hv1[8], hv2[8];
#pragma unroll
    for (int q = 0; q < 8; q++) { hv0[q] = 0ull; hv1[q] = 0ull; hv2[q] = 0ull; }
#pragma unroll
    for (int qw = 0; qw < 8; qw++) {
        float2 v0 = unpk2(yv0[qw]);
        float2 v1 = unpk2(yv1[qw]);
        float2 v2 = unpk2(yv2[qw]);
        {
            U64 p0 = pack2(v0.x, v0.x), p1 = pack2(v1.x, v1.x), p2 = pack2(v2.x, v2.x);
            const U64* wr = (const U64*)(s12V + (2 * qw) * 16);
#pragma unroll
            for (int q = 0; q < 8; q++) {
                U64 w = wr[q];
                fma2(hv0[q], w, p0);
                fma2(hv1[q], w, p1);
                fma2(hv2[q], w, p2);
            }
        }
        {
            U64 p0 = pack2(v0.y, v0.y), p1 = pack2(v1.y, v1.y), p2 = pack2(v2.y, v2.y);
            const U64* wr = (const U64*)(s12V + (2 * qw + 1) * 16);
#pragma unroll
            for (int q = 0; q < 8; q++) {
                U64 w = wr[q];
                fma2(hv0[q], w, p0);
                fma2(hv1[q], w, p1);
                fma2(hv2[q], w, p2);
            }
        }
    }

    float* hvd = g_hv + (size_t)n * 48;
#pragma unroll
    for (int q = 0; q < 8; q++) {
        float2 f0 = unpk2(hv0[q]);
        float2 f1 = unpk2(hv1[q]);
        float2 f2 = unpk2(hv2[q]);
        hvd[6 * q + 0] = f0.x * s;
        hvd[6 * q + 1] = f1.x * s;
        hvd[6 * q + 2] = f2.x * s;
        hvd[6 * q + 3] = f0.y * s;
        hvd[6 * q + 4] = f1.y * s;
        hvd[6 * q + 5] = f2.y * s;
    }
}

// ---------------------------------------------------------------------------
// Kernel D: edge pass 2 (fp16 smem H, coalesced elen, 6 blocks/SM)
// sU[3072]: {W1[640] | sEL[1280]@640} -> W2[3072]
// sBUF[48*SOS]: elen-linear -> H fp16 [64][128] -> sOUT fp32 [48][SOS]
// ---------------------------------------------------------------------------
__global__ __launch_bounds__(128, 6)
void k_edge2(const float* __restrict__ elen, const float* __restrict__ eattr,
             const int* __restrict__ esrc, const int* __restrict__ edst,
             const float* __restrict__ W1, const float* __restrict__ W2, int E)
{
    __shared__ __align__(16) float sU[3072];
    __shared__ __align__(16) float sBUF[48 * SOS];

    float* sEL = sU + 640;
    __half* sHh = (__half*)sBUF;
    float* sOUT = sBUF;

    int t = threadIdx.x;
    int warp = t >> 5, lane = t & 31;
    int colb = 4 * lane;
    int hb = warp * 16;
    int ob = warp * 12;
    int j = lane & 3;
    int g = lane >> 2;

    for (int i = t; i < 640; i += 128) sU[i] = W1[i];

    int blockBase = blockIdx.x * EPB;
    int e = blockBase + t;
    int eL = e < E ? e : E - 1;

    int srcIdx = esrc[eL];
    int dstIdx = edst[eL];
    float4 ea = ((const float4*)eattr)[eL];

    {
        int gbase = blockBase * 10;
        int lim = E * 10;
#pragma unroll
        for (int i = 0; i < 10; i++) {
            int gi = gbase + i * 128 + t;
            sBUF[i * 128 + t] = (gi < lim) ? elen[gi] : 0.f;
        }
        __syncthreads();
        const float2* rp = (const float2*)(sBUF + t * 10);
        float el[10];
#pragma unroll
        for (int i = 0; i < 5; i++) {
            float2 v = rp[i];
            el[2 * i] = v.x; el[2 * i + 1] = v.y;
        }
        __syncthreads();
#pragma unroll
        for (int i = 0; i < 10; i++) sEL[i * 128 + t] = el[i];
    }
    __syncthreads();

#pragma unroll
    for (int half = 0; half < 2; half++) {
        int hbh = hb + 8 * half;
        U64 hacc[4][4];
#pragma unroll
        for (int a = 0; a < 4; a++)
#pragma unroll
            for (int b = 0; b < 4; b++) hacc[a][b] = 0ull;

#pragma unroll
        for (int k = 0; k < 10; k++) {
            float4 x4 = *(const float4*)(sEL + k * 128 + colb);
            const ulonglong2* wp = (const ulonglong2*)(sU + k * 64 + hbh);
            ulonglong2 w0 = wp[0], w1 = wp[1];
            float xs4[4] = { x4.x, x4.y, x4.z, x4.w };
#pragma unroll
            for (int ei = 0; ei < 4; ei++) {
                U64 xx = pack2(xs4[ei], xs4[ei]);
                fma2(hacc[ei][0], w0.x, xx); fma2(hacc[ei][1], w0.y, xx);
                fma2(hacc[ei][2], w1.x, xx); fma2(hacc[ei][3], w1.y, xx);
            }
        }
#pragma unroll
        for (int jp = 0; jp < 4; jp++) {
            float2 f[4];
#pragma unroll
            for (int ei = 0; ei < 4; ei++) {
                f[ei] = unpk2(hacc[ei][jp]);
                f[ei].x = fast_silu(f[ei].x * INV_SQRT10);
                f[ei].y = fast_silu(f[ei].y * INV_SQRT10);
            }
            *(uint2*)(sHh + (hbh + 2 * jp) * 128 + colb) =
                make_uint2(h2bits(f[0].x, f[1].x), h2bits(f[2].x, f[3].x));
            *(uint2*)(sHh + (hbh + 2 * jp + 1) * 128 + colb) =
                make_uint2(h2bits(f[0].y, f[1].y), h2bits(f[2].y, f[3].y));
        }
    }
    __syncthreads();

    for (int i = t; i < 3072; i += 128) sU[i] = W2[i];
    __syncthreads();

    U64 acc[4][6];
#pragma unroll
    for (int a = 0; a < 4; a++)
#pragma unroll
        for (int b = 0; b < 6; b++) acc[a][b] = 0ull;

#pragma unroll 8
    for (int k = 0; k < 64; k++) {
        uint2 hr = *(const uint2*)(sHh + k * 128 + colb);
        float2 fa = h2f2(hr.x), fb = h2f2(hr.y);
        const ulonglong2* wp = (const ulonglong2*)(sU + k * 48 + ob);
        ulonglong2 wa = wp[0], wb = wp[1], wc = wp[2];
        float hs[4] = { fa.x, fa.y, fb.x, fb.y };
#pragma unroll
        for (int ei = 0; ei < 4; ei++) {
            U64 xx = pack2(hs[ei], hs[ei]);
            fma2(acc[ei][0], wa.x, xx); fma2(acc[ei][1], wa.y, xx);
            fma2(acc[ei][2], wb.x, xx); fma2(acc[ei][3], wb.y, xx);
            fma2(acc[ei][4], wc.x, xx); fma2(acc[ei][5], wc.y, xx);
        }
    }
    __syncthreads();

#pragma unroll
    for (int op = 0; op < 6; op++) {
        float2 f[4];
#pragma unroll
        for (int ei = 0; ei < 4; ei++) f[ei] = unpk2(acc[ei][op]);
        int r0 = ob + 2 * op, r1 = ob + 2 * op + 1;
        *(float4*)(sOUT + SWIZ(r0, colb)) =
            make_float4(f[0].x * INV8, f[1].x * INV8, f[2].x * INV8, f[3].x * INV8);
        *(float4*)(sOUT + SWIZ(r1, colb)) =
            make_float4(f[0].y * INV8, f[1].y * INV8, f[2].y * INV8, f[3].y * INV8);
    }
    __syncthreads();

#pragma unroll
    for (int p = 0; p < 4; p++) {
        int q = 8 * p + g;
        int eQ = blockBase + 32 * warp + q;
        int sE  = __shfl_sync(0xffffffffu, srcIdx, q);
        int dE  = __shfl_sync(0xffffffffu, dstIdx, q);
        float eax = __shfl_sync(0xffffffffu, ea.x, q);
        float eay = __shfl_sync(0xffffffffu, ea.y, q);
        float eaz = __shfl_sync(0xffffffffu, ea.z, q);
        float eaw = __shfl_sync(0xffffffffu, ea.w, q);
        if (eQ < E) {
            int col = 32 * warp + q;
            float* m2 = g_mid2 + (size_t)dE * 48;
            const float4* gp = (const float4*)(g_h0 + (size_t)sE * 32 + 8 * j);
            float4 a0 = gp[0], a1 = gp[1];
            float w0 = sOUT[SWIZ(8 * j + 0, col)];
            float w1 = sOUT[SWIZ(8 * j + 1, col)];
            float w2 = sOUT[SWIZ(8 * j + 2, col)];
            float w3 = sOUT[SWIZ(8 * j + 3, col)];
            float w4 = sOUT[SWIZ(8 * j + 4, col)];
            float w5 = sOUT[SWIZ(8 * j + 5, col)];
            float w6 = sOUT[SWIZ(8 * j + 6, col)];
            float w7 = sOUT[SWIZ(8 * j + 7, col)];
            red4(m2 + 8 * j,     a0.x * eax * w0, a0.y * eax * w1,
                                 a0.z * eax * w2, a0.w * eax * w3);
            red4(m2 + 8 * j + 4, a1.x * eax * w4, a1.y * eax * w5,
                                 a1.z * eax * w6, a1.w * eax * w7);
            const float4* vp = (const float4*)(g_hv + (size_t)sE * 48 + 12 * j);
            float4 b0 = vp[0], b1 = vp[1], b2 = vp[2];
            float wv0 = sOUT[SWIZ(32 + 4 * j + 0, col)];
            float wv1 = sOUT[SWIZ(32 + 4 * j + 1, col)];
            float wv2 = sOUT[SWIZ(32 + 4 * j + 2, col)];
            float wv3 = sOUT[SWIZ(32 + 4 * j + 3, col)];
            float dv0 = (b0.x * eay + b0.y * eaz + b0.z * eaw) * INV_SQRT3 * wv0;
            float dv1 = (b0.w * eay + b1.x * eaz + b1.y * eaw) * INV_SQRT3 * wv1;
            float dv2 = (b1.z * eay + b1.w * eaz + b2.x * eaw) * INV_SQRT3 * wv2;
            float dv3 = (b2.y * eay + b2.z * eaz + b2.w * eaw) * INV_SQRT3 * wv3;
            red4(m2 + 32 + 4 * j, dv0, dv1, dv2, dv3);
        }
    }
}

// ---------------------------------------------------------------------------
// Kernel E: final node readout
// ---------------------------------------------------------------------------
__global__ __launch_bounds__(128)
void k_node3(const float* __restrict__ na, const float* __restrict__ Wl22,
             float* __restrict__ out, int N)
{
    __shared__ float sw[48];
    for (int i = threadIdx.x; i < 48; i += 128) sw[i] = Wl22[i];
    __syncthreads();

    int n = blockIdx.x * 128 + threadIdx.x;
    if (n >= N) return;

    float acc = 0.f;
    const float4* mp = (const float4*)(g_mid2 + (size_t)n * 48);
#pragma unroll
    for (int i = 0; i < 12; i++) {
        float4 t = mp[i];
        acc += t.x * sw[4 * i] + t.y * sw[4 * i + 1] + t.z * sw[4 * i + 2] + t.w * sw[4 * i + 3];
    }
    float x = acc * INV4 * INV_SQRT48 * na[n];
    out[n] = C_S * g_s2[n] + C_X * x;
}

// ---------------------------------------------------------------------------
// Launch
// ---------------------------------------------------------------------------
extern "C" void kernel_launch(void* const* d_in, const int* in_sizes, int n_in,
                              void* d_out, int out_size)
{
    const float* node_input = (const float*)d_in[0];
    const float* node_attr  = (const float*)d_in[1];
    const float* edge_attr  = (const float*)d_in[2];
    const float* elen       = (const float*)d_in[3];
    const float* W_sc1      = (const float*)d_in[4];
    const float* W_lin1_1   = (const float*)d_in[5];
    const float* fc1_W1     = (const float*)d_in[6];
    const float* fc1_W2     = (const float*)d_in[7];
    const float* W_l2s_1    = (const float*)d_in[8];
    const float* W_l2v_1    = (const float*)d_in[9];
    const float* W_sc2      = (const float*)d_in[10];
    const float* W_lin1_2s  = (const float*)d_in[11];
    const float* W_lin1_2v  = (const float*)d_in[12];
    const float* fc2_W1     = (const float*)d_in[13];
    const float* fc2_W2     = (const float*)d_in[14];
    const float* W_lin2_2   = (const float*)d_in[15];
    const int*   esrc       = (const int*)d_in[16];
    const int*   edst       = (const int*)d_in[17];
    float* out = (float*)d_out;

    int N = in_sizes[1];
    int E = in_sizes[16];
    int eblocks = (E + EPB - 1) / EPB;

    k_node1<<<(N + 127) / 128, 128>>>(node_input, node_attr, W_sc1, W_lin1_1, N);
    k_edge1<<<eblocks, 128>>>(elen, edge_attr, esrc, edst, fc1_W1, fc1_W2, E);
    k_node2<<<(N + 127) / 128, 128>>>(node_attr, W_l2s_1, W_l2v_1, W_sc2,
                                      W_lin1_2s, W_lin1_2v, N);
    k_edge2<<<eblocks, 128>>>(elen, edge_attr, esrc, edst, fc2_W1, fc2_W2, E);
    k_node3<<<(N + 127) / 128, 128>>>(node_attr, W_lin2_2, out, N);
}

// round 15
// speedup vs baseline: 1.0569x; 1.0569x over previous
#include <cuda_runtime.h>

#define EPB 128

#define INV4        0.25f
#define INV_SQRT10  0.3162277660168379f
#define INV8        0.125f
#define INV_SQRT32  0.1767766952966369f
#define INV_SQRT48  0.1443375672974064f
#define INV_SQRT3   0.5773502691896258f
#define C_S         0.3826834323650898f
#define C_X         0.9238795325112867f

#define N_NODES_MAX 100000
#define SOS 132   // sOUT padded stride

// XOR swizzle for sOUT column reads (R8, proven)
#define SWX(r)      (8 * (((r) >> 3) & 3))
#define SWIZ(r, c)  ((r) * SOS + ((c) ^ SWX(r)))

typedef unsigned long long U64;

// ---------------------------------------------------------------------------
// Scratch
// ---------------------------------------------------------------------------
__device__ __align__(16) float g_sscal[(size_t)N_NODES_MAX * 48];
__device__ __align__(16) float g_x1  [(size_t)N_NODES_MAX * 16];
__device__ __align__(16) float g_mid [(size_t)N_NODES_MAX * 64];
__device__ __align__(16) float g_s2  [(size_t)N_NODES_MAX];
__device__ __align__(16) float g_h0  [(size_t)N_NODES_MAX * 32];
__device__ __align__(16) float g_hv  [(size_t)N_NODES_MAX * 48];
__device__ __align__(16) float g_mid2[(size_t)N_NODES_MAX * 48];

__device__ __forceinline__ float fast_sigmoid(float x) {
    return __fdividef(1.0f, 1.0f + __expf(-x));
}
__device__ __forceinline__ float fast_silu(float x) {
    return __fdividef(x, 1.0f + __expf(-x));
}

__device__ __forceinline__ U64 pack2(float a, float b) {
    U64 r; asm("mov.b64 %0, {%1, %2};" : "=l"(r) : "f"(a), "f"(b)); return r;
}
__device__ __forceinline__ float2 unpk2(U64 v) {
    float2 r; asm("mov.b64 {%0, %1}, %2;" : "=f"(r.x), "=f"(r.y) : "l"(v)); return r;
}
__device__ __forceinline__ void fma2(U64& d, U64 a, U64 b) {
    asm("fma.rn.f32x2 %0, %1, %2, %0;" : "+l"(d) : "l"(a), "l"(b));
}
__device__ __forceinline__ void mul2(U64& d, U64 a) {
    asm("mul.rn.f32x2 %0, %0, %1;" : "+l"(d) : "l"(a));
}
__device__ __forceinline__ void red4(float* addr, float a, float b, float c, float d) {
    asm volatile("red.global.add.v4.f32 [%0], {%1, %2, %3, %4};"
                 :: "l"(addr), "f"(a), "f"(b), "f"(c), "f"(d) : "memory");
}

// ---------------------------------------------------------------------------
// Kernel A: per-node precompute; coalesced stores via smem transpose;
// linear zeroing of mid/mid2
// ---------------------------------------------------------------------------
__global__ __launch_bounds__(128)
void k_node1(const float* __restrict__ ni, const float* __restrict__ na,
             const float* __restrict__ Wsc1, const float* __restrict__ Wl11, int N)
{
    __shared__ __align__(16) float sA[16 * 48];
    __shared__ __align__(16) float sB[16 * 16];
    __shared__ float sbuf[128 * 49];
    for (int i = threadIdx.x; i < 16 * 48; i += 128) sA[i] = Wsc1[i];
    for (int i = threadIdx.x; i < 16 * 16; i += 128) sB[i] = Wl11[i];
    __syncthreads();

    int t = threadIdx.x;
    int blockBase = blockIdx.x * 128;
    int n = blockBase + t;
    int nv = N - blockBase; if (nv > 128) nv = 128;
    bool valid = (t < nv);

    U64 sc2[24], xv2[8];
    float a = 0.f;
    if (valid) {
        float in[16];
        const float4* p = (const float4*)(ni + (size_t)n * 16);
#pragma unroll
        for (int i = 0; i < 4; i++) {
            float4 v = p[i];
            in[4 * i] = v.x; in[4 * i + 1] = v.y; in[4 * i + 2] = v.z; in[4 * i + 3] = v.w;
        }
        a = na[n];

#pragma unroll
        for (int c = 0; c < 24; c++) sc2[c] = 0ull;
#pragma unroll
        for (int j = 0; j < 8; j++) xv2[j] = 0ull;

#pragma unroll
        for (int k = 0; k < 16; k++) {
            U64 xx = pack2(in[k], in[k]);
            const ulonglong2* wa = (const ulonglong2*)(sA + k * 48);
#pragma unroll
            for (int c4 = 0; c4 < 12; c4++) {
                ulonglong2 w = wa[c4];
                fma2(sc2[2 * c4], w.x, xx);
                fma2(sc2[2 * c4 + 1], w.y, xx);
            }
            const ulonglong2* wb = (const ulonglong2*)(sB + k * 16);
#pragma unroll
            for (int j4 = 0; j4 < 4; j4++) {
                ulonglong2 w = wb[j4];
                fma2(xv2[2 * j4], w.x, xx);
                fma2(xv2[2 * j4 + 1], w.y, xx);
            }
        }
    }

    float sa = INV4 * a;
    // stage sscal -> coalesced store
    if (valid) {
#pragma unroll
        for (int c = 0; c < 24; c++) {
            float2 f = unpk2(sc2[c]);
            sbuf[t * 49 + 2 * c]     = f.x * sa;
            sbuf[t * 49 + 2 * c + 1] = f.y * sa;
        }
    }
    __syncthreads();
    for (int i = t; i < nv * 48; i += 128)
        g_sscal[(size_t)blockBase * 48 + i] = sbuf[(i / 48) * 49 + (i % 48)];
    __syncthreads();

    // stage x1 -> coalesced store
    if (valid) {
#pragma unroll
        for (int j = 0; j < 8; j++) {
            float2 f = unpk2(xv2[j]);
            sbuf[t * 17 + 2 * j]     = f.x * sa;
            sbuf[t * 17 + 2 * j + 1] = f.y * sa;
        }
    }
    __syncthreads();
    for (int i = t; i < nv * 16; i += 128)
        g_x1[(size_t)blockBase * 16 + i] = sbuf[(i / 16) * 17 + (i % 16)];

    // coalesced linear zeroing of mid & mid2 (block-local slices)
    for (int i = t; i < nv * 64; i += 128) g_mid [(size_t)blockBase * 64 + i] = 0.f;
    for (int i = t; i < nv * 48; i += 128) g_mid2[(size_t)blockBase * 48 + i] = 0.f;
}

// ---------------------------------------------------------------------------
// Kernel B: edge pass 1 (R12 exact — frozen)
// ---------------------------------------------------------------------------
__global__ __launch_bounds__(128, 5)
void k_edge1(const float* __restrict__ elen, const float* __restrict__ eattr,
             const int* __restrict__ esrc, const int* __restrict__ edst,
             const float* __restrict__ W1, const float* __restrict__ W2, int E)
{
    __shared__ __align__(16) float sU[2048];
    __shared__ __align__(16) float sH[64 * 128];

    float* sEL = sU + 640;

    int t = threadIdx.x;
    int warp = t >> 5, lane = t & 31;
    int colb = 4 * lane;
    int hb = warp * 16;
    int ob = warp * 8;
    int j = lane & 3;
    int g = lane >> 2;

    for (int i = t; i < 640; i += 128) sU[i] = W1[i];

    int blockBase = blockIdx.x * EPB;
    int e = blockBase + t;
    int eL = e < E ? e : E - 1;

    int srcIdx = esrc[eL];
    int dstIdx = edst[eL];
    float4 ea = ((const float4*)eattr)[eL];

    {
        const float2* ep = (const float2*)(elen + (size_t)eL * 10);
#pragma unroll
        for (int i = 0; i < 5; i++) {
            float2 v = ep[i];
            sEL[(2 * i) * 128 + t]     = v.x;
            sEL[(2 * i + 1) * 128 + t] = v.y;
        }
    }
    __syncthreads();

#pragma unroll
    for (int half = 0; half < 2; half++) {
        int hbh = hb + 8 * half;
        U64 hacc[4][4];
#pragma unroll
        for (int a = 0; a < 4; a++)
#pragma unroll
            for (int b = 0; b < 4; b++) hacc[a][b] = 0ull;

#pragma unroll
        for (int k = 0; k < 10; k++) {
            float4 x4 = *(const float4*)(sEL + k * 128 + colb);
            const ulonglong2* wp = (const ulonglong2*)(sU + k * 64 + hbh);
            ulonglong2 w0 = wp[0], w1 = wp[1];
            float xs4[4] = { x4.x, x4.y, x4.z, x4.w };
#pragma unroll
            for (int ei = 0; ei < 4; ei++) {
                U64 xx = pack2(xs4[ei], xs4[ei]);
                fma2(hacc[ei][0], w0.x, xx); fma2(hacc[ei][1], w0.y, xx);
                fma2(hacc[ei][2], w1.x, xx); fma2(hacc[ei][3], w1.y, xx);
            }
        }
#pragma unroll
        for (int jp = 0; jp < 4; jp++) {
            float2 f[4];
#pragma unroll
            for (int ei = 0; ei < 4; ei++) {
                f[ei] = unpk2(hacc[ei][jp]);
                f[ei].x = fast_silu(f[ei].x * INV_SQRT10);
                f[ei].y = fast_silu(f[ei].y * INV_SQRT10);
            }
            *(float4*)(sH + (hbh + 2 * jp) * 128 + colb) =
                make_float4(f[0].x, f[1].x, f[2].x, f[3].x);
            *(float4*)(sH + (hbh + 2 * jp + 1) * 128 + colb) =
                make_float4(f[0].y, f[1].y, f[2].y, f[3].y);
        }
    }
    __syncthreads();

    for (int i = t; i < 2048; i += 128) sU[i] = W2[i];
    __syncthreads();

    U64 acc[4][4];
#pragma unroll
    for (int a = 0; a < 4; a++)
#pragma unroll
        for (int b = 0; b < 4; b++) acc[a][b] = 0ull;

#pragma unroll 8
    for (int k = 0; k < 64; k++) {
        float4 h4 = *(const float4*)(sH + k * 128 + colb);
        const ulonglong2* wp = (const ulonglong2*)(sU + k * 32 + ob);
        ulonglong2 wa = wp[0], wb = wp[1];
        float hs[4] = { h4.x, h4.y, h4.z, h4.w };
#pragma unroll
        for (int ei = 0; ei < 4; ei++) {
            U64 xx = pack2(hs[ei], hs[ei]);
            fma2(acc[ei][0], wa.x, xx); fma2(acc[ei][1], wa.y, xx);
            fma2(acc[ei][2], wb.x, xx); fma2(acc[ei][3], wb.y, xx);
        }
    }
    __syncthreads();

    float* sOUT = sH;
#pragma unroll
    for (int op = 0; op < 4; op++) {
        float2 f[4];
#pragma unroll
        for (int ei = 0; ei < 4; ei++) f[ei] = unpk2(acc[ei][op]);
        int r0 = ob + 2 * op, r1 = ob + 2 * op + 1;
        *(float4*)(sOUT + SWIZ(r0, colb)) =
            make_float4(f[0].x * INV8, f[1].x * INV8, f[2].x * INV8, f[3].x * INV8);
        *(float4*)(sOUT + SWIZ(r1, colb)) =
            make_float4(f[0].y * INV8, f[1].y * INV8, f[2].y * INV8, f[3].y * INV8);
    }
    __syncthreads();

#pragma unroll
    for (int p = 0; p < 4; p++) {
        int q = 8 * p + g;
        int eQ = blockBase + 32 * warp + q;
        int sE  = __shfl_sync(0xffffffffu, srcIdx, q);
        int dE  = __shfl_sync(0xffffffffu, dstIdx, q);
        float eax = __shfl_sync(0xffffffffu, ea.x, q);
        float eay = __shfl_sync(0xffffffffu, ea.y, q);
        float eaz = __shfl_sync(0xffffffffu, ea.z, q);
        float eaw = __shfl_sync(0xffffffffu, ea.w, q);
        if (eQ < E) {
            int col = 32 * warp + q;
            float4 x = *(const float4*)(g_x1 + (size_t)sE * 16 + 4 * j);
            float* mrow = g_mid + (size_t)dE * 64;
            float w0 = sOUT[SWIZ(4 * j + 0, col)];
            float w1 = sOUT[SWIZ(4 * j + 1, col)];
            float w2 = sOUT[SWIZ(4 * j + 2, col)];
            float w3 = sOUT[SWIZ(4 * j + 3, col)];
            red4(mrow + 4 * j, x.x * eax * w0, x.y * eax * w1,
                               x.z * eax * w2, x.w * eax * w3);
            float t0 = x.x * sOUT[SWIZ(16 + 4 * j + 0, col)];
            float t1 = x.y * sOUT[SWIZ(16 + 4 * j + 1, col)];
            float t2 = x.z * sOUT[SWIZ(16 + 4 * j + 2, col)];
            float t3 = x.w * sOUT[SWIZ(16 + 4 * j + 3, col)];
            float* f1p = mrow + 16 + 12 * j;
            red4(f1p + 0, t0 * eay, t0 * eaz, t0 * eaw, t1 * eay);
            red4(f1p + 4, t1 * eaz, t1 * eaw, t2 * eay, t2 * eaz);
            red4(f1p + 8, t2 * eaw, t3 * eay, t3 * eaz, t3 * eaw);
        }
    }
}

// ---------------------------------------------------------------------------
// Kernel C: per-node mid processing (R12 compute; coalesced h0/hv stores)
// ---------------------------------------------------------------------------
__global__ __launch_bounds__(128)
void k_node2(const float* __restrict__ na,
             const float* __restrict__ Wl2s, const float* __restrict__ Wl2v,
             const float* __restrict__ Wsc2, const float* __restrict__ W12s,
             const float* __restrict__ W12v, int N)
{
    __shared__ __align__(16) float sL2S[16 * 48];
    __shared__ __align__(16) float sL2V[16 * 16];
    __shared__ float sSC2[32];
    __shared__ __align__(16) float s12S[32 * 32];
    __shared__ __align__(16) float s12V[16 * 16];
    __shared__ float sbuf[128 * 49];
    for (int i = threadIdx.x; i < 16 * 48; i += 128) sL2S[i] = Wl2s[i];
    for (int i = threadIdx.x; i < 16 * 16; i += 128) sL2V[i] = Wl2v[i];
    for (int i = threadIdx.x; i < 32;      i += 128) sSC2[i] = Wsc2[i];
    for (int i = threadIdx.x; i < 32 * 32; i += 128) s12S[i] = W12s[i];
    for (int i = threadIdx.x; i < 16 * 16; i += 128) s12V[i] = W12v[i];
    __syncthreads();

    int t = threadIdx.x;
    int blockBase = blockIdx.x * 128;
    int n = blockBase + t;
    int nv = N - blockBase; if (nv > 128) nv = 128;
    bool valid = (t < nv);

    float a = 0.f;
    float s = 0.f;
    const float4* mp = (const float4*)(g_mid + (size_t)(valid ? n : 0) * 64);

    U64 h02[16];
    float gs[16];
    if (valid) {
        a = na[n];
        s = INV4 * a;

        float m0[16];
#pragma unroll
        for (int i = 0; i < 4; i++) {
            float4 v = mp[i];
            m0[4 * i] = v.x * INV4; m0[4 * i + 1] = v.y * INV4;
            m0[4 * i + 2] = v.z * INV4; m0[4 * i + 3] = v.w * INV4;
        }
        U64 ys2[24];
#pragma unroll
        for (int c = 0; c < 24; c++) ys2[c] = 0ull;
#pragma unroll
        for (int u = 0; u < 16; u++) {
            U64 xx = pack2(m0[u], m0[u]);
            const ulonglong2* wr = (const ulonglong2*)(sL2S + u * 48);
#pragma unroll
            for (int c4 = 0; c4 < 12; c4++) {
                ulonglong2 w = wr[c4];
                fma2(ys2[2 * c4], w.x, xx);
                fma2(ys2[2 * c4 + 1], w.y, xx);
            }
        }

        const float4* ssp = (const float4*)(g_sscal + (size_t)n * 48);
        float scal[32];
#pragma unroll
        for (int i = 0; i < 8; i++) {
            float4 ss = ssp[i];
            float2 y0 = unpk2(ys2[2 * i]);
            float2 y1 = unpk2(ys2[2 * i + 1]);
            scal[4 * i + 0] = fast_silu(C_S * ss.x + C_X * (y0.x * s));
            scal[4 * i + 1] = fast_silu(C_S * ss.y + C_X * (y0.y * s));
            scal[4 * i + 2] = fast_silu(C_S * ss.z + C_X * (y1.x * s));
            scal[4 * i + 3] = fast_silu(C_S * ss.w + C_X * (y1.y * s));
        }
#pragma unroll
        for (int i = 0; i < 4; i++) {
            float4 ss = ssp[8 + i];
            float2 y0 = unpk2(ys2[16 + 2 * i]);
            float2 y1 = unpk2(ys2[16 + 2 * i + 1]);
            gs[4 * i + 0] = fast_sigmoid(C_S * ss.x + C_X * (y0.x * s)) * s;
            gs[4 * i + 1] = fast_sigmoid(C_S * ss.y + C_X * (y0.y * s)) * s;
            gs[4 * i + 2] = fast_sigmoid(C_S * ss.z + C_X * (y1.x * s)) * s;
            gs[4 * i + 3] = fast_sigmoid(C_S * ss.w + C_X * (y1.y * s)) * s;
        }

        float s2v = 0.f;
#pragma unroll
        for (int o = 0; o < 32; o++) s2v += scal[o] * sSC2[o];
        g_s2[n] = s2v * INV_SQRT32 * a;

#pragma unroll
        for (int p = 0; p < 16; p++) h02[p] = 0ull;
#pragma unroll
        for (int o = 0; o < 32; o++) {
            U64 xx = pack2(scal[o], scal[o]);
            const ulonglong2* wr = (const ulonglong2*)(s12S + o * 32);
#pragma unroll
            for (int p4 = 0; p4 < 8; p4++) {
                ulonglong2 w = wr[p4];
                fma2(h02[2 * p4], w.x, xx);
                fma2(h02[2 * p4 + 1], w.y, xx);
            }
        }
    }

    // stage h0 -> coalesced store
    if (valid) {
        float sh = INV_SQRT32 * a;
#pragma unroll
        for (int p = 0; p < 16; p++) {
            float2 f = unpk2(h02[p]);
            sbuf[t * 33 + 2 * p]     = f.x * sh;
            sbuf[t * 33 + 2 * p + 1] = f.y * sh;
        }
    }
    __syncthreads();
    for (int i = t; i < nv * 32; i += 128)
        g_h0[(size_t)blockBase * 32 + i] = sbuf[(i / 32) * 33 + (i % 32)];
    __syncthreads();

    // yv / hv
    U64 hv0[8], hv1[8], hv2[8];
    if (valid) {
        float m1[48];
#pragma unroll
        for (int i = 0; i < 12; i++) {
            float4 v = mp[4 + i];
            m1[4 * i] = v.x * INV4; m1[4 * i + 1] = v.y * INV4;
            m1[4 * i + 2] = v.z * INV4; m1[4 * i + 3] = v.w * INV4;
        }
        U64 yv0[8], yv1[8], yv2[8];
#pragma unroll
        for (int q = 0; q < 8; q++) { yv0[q] = 0ull; yv1[q] = 0ull; yv2[q] = 0ull; }
#pragma unroll
        for (int u = 0; u < 16; u++) {
            U64 p0 = pack2(m1[3 * u + 0], m1[3 * u + 0]);
            U64 p1 = pack2(m1[3 * u + 1], m1[3 * u + 1]);
            U64 p2 = pack2(m1[3 * u + 2], m1[3 * u + 2]);
            const U64* wr = (const U64*)(sL2V + u * 16);
#pragma unroll
            for (int q = 0; q < 8; q++) {
                U64 w = wr[q];
                fma2(yv0[q], w, p0);
                fma2(yv1[q], w, p1);
                fma2(yv2[q], w, p2);
            }
        }
#pragma unroll
        for (int q = 0; q < 8; q++) {
            U64 gp = pack2(gs[2 * q], gs[2 * q + 1]);
            mul2(yv0[q], gp);
            mul2(yv1[q], gp);
            mul2(yv2[q], gp);
        }

#pragma unroll
        for (int q = 0; q < 8; q++) { hv0[q] = 0ull; hv1[q] = 0ull; hv2[q] = 0ull; }
#pragma unroll
        for (int qw = 0; qw < 8; qw++) {
            float2 v0 = unpk2(yv0[qw]);
            float2 v1 = unpk2(yv1[qw]);
            float2 v2 = unpk2(yv2[qw]);
            {
                U64 p0 = pack2(v0.x, v0.x), p1 = pack2(v1.x, v1.x), p2 = pack2(v2.x, v2.x);
                const U64* wr = (const U64*)(s12V + (2 * qw) * 16);
#pragma unroll
                for (int q = 0; q < 8; q++) {
                    U64 w = wr[q];
                    fma2(hv0[q], w, p0);
                    fma2(hv1[q], w, p1);
                    fma2(hv2[q], w, p2);
                }
            }
            {
                U64 p0 = pack2(v0.y, v0.y), p1 = pack2(v1.y, v1.y), p2 = pack2(v2.y, v2.y);
                const U64* wr = (const U64*)(s12V + (2 * qw + 1) * 16);
#pragma unroll
                for (int q = 0; q < 8; q++) {
                    U64 w = wr[q];
                    fma2(hv0[q], w, p0);
                    fma2(hv1[q], w, p1);
                    fma2(hv2[q], w, p2);
                }
            }
        }
    }

    // stage hv -> coalesced store
    if (valid) {
#pragma unroll
        for (int q = 0; q < 8; q++) {
            float2 f0 = unpk2(hv0[q]);
            float2 f1 = unpk2(hv1[q]);
            float2 f2 = unpk2(hv2[q]);
            sbuf[t * 49 + 6 * q + 0] = f0.x * s;
            sbuf[t * 49 + 6 * q + 1] = f1.x * s;
            sbuf[t * 49 + 6 * q + 2] = f2.x * s;
            sbuf[t * 49 + 6 * q + 3] = f0.y * s;
            sbuf[t * 49 + 6 * q + 4] = f1.y * s;
            sbuf[t * 49 + 6 * q + 5] = f2.y * s;
        }
    }
    __syncthreads();
    for (int i = t; i < nv * 48; i += 128)
        g_hv[(size_t)blockBase * 48 + i] = sbuf[(i / 48) * 49 + (i % 48)];
}

// ---------------------------------------------------------------------------
// Kernel D: edge pass 2 (R12 exact — frozen)
// ---------------------------------------------------------------------------
__global__ __launch_bounds__(128, 5)
void k_edge2(const float* __restrict__ elen, const float* __restrict__ eattr,
             const int* __restrict__ esrc, const int* __restrict__ edst,
             const float* __restrict__ W1, const float* __restrict__ W2, int E)
{
    __shared__ __align__(16) float sU[3072];
    __shared__ __align__(16) float sH[64 * 128];

    float* sEL = sU + 640;

    int t = threadIdx.x;
    int warp = t >> 5, lane = t & 31;
    int colb = 4 * lane;
    int hb = warp * 16;
    int ob = warp * 12;
    int j = lane & 3;
    int g = lane >> 2;

    for (int i = t; i < 640; i += 128) sU[i] = W1[i];

    int blockBase = blockIdx.x * EPB;
    int e = blockBase + t;
    int eL = e < E ? e : E - 1;

    int srcIdx = esrc[eL];
    int dstIdx = edst[eL];
    float4 ea = ((const float4*)eattr)[eL];

    {
        const float2* ep = (const float2*)(elen + (size_t)eL * 10);
#pragma unroll
        for (int i = 0; i < 5; i++) {
            float2 v = ep[i];
            sEL[(2 * i) * 128 + t]     = v.x;
            sEL[(2 * i + 1) * 128 + t] = v.y;
        }
    }
    __syncthreads();

#pragma unroll
    for (int half = 0; half < 2; half++) {
        int hbh = hb + 8 * half;
        U64 hacc[4][4];
#pragma unroll
        for (int a = 0; a < 4; a++)
#pragma unroll
            for (int b = 0; b < 4; b++) hacc[a][b] = 0ull;

#pragma unroll
        for (int k = 0; k < 10; k++) {
            float4 x4 = *(const float4*)(sEL + k * 128 + colb);
            const ulonglong2* wp = (const ulonglong2*)(sU + k * 64 + hbh);
            ulonglong2 w0 = wp[0], w1 = wp[1];
            float xs4[4] = { x4.x, x4.y, x4.z, x4.w };
#pragma unroll
            for (int ei = 0; ei < 4; ei++) {
                U64 xx = pack2(xs4[ei], xs4[ei]);
                fma2(hacc[ei][0], w0.x, xx); fma2(hacc[ei][1], w0.y, xx);
                fma2(hacc[ei][2], w1.x, xx); fma2(hacc[ei][3], w1.y, xx);
            }
        }
#pragma unroll
        for (int jp = 0; jp < 4; jp++) {
            float2 f[4];
#pragma unroll
            for (int ei = 0; ei < 4; ei++) {
                f[ei] = unpk2(hacc[ei][jp]);
                f[ei].x = fast_silu(f[ei].x * INV_SQRT10);
                f[ei].y = fast_silu(f[ei].y * INV_SQRT10);
            }
            *(float4*)(sH + (hbh + 2 * jp) * 128 + colb) =
                make_float4(f[0].x, f[1].x, f[2].x, f[3].x);
            *(float4*)(sH + (hbh + 2 * jp + 1) * 128 + colb) =
                make_float4(f[0].y, f[1].y, f[2].y, f[3].y);
        }
    }
    __syncthreads();

    for (int i = t; i < 3072; i += 128) sU[i] = W2[i];
    __syncthreads();

    U64 acc[4][6];
#pragma unroll
    for (int a = 0; a < 4; a++)
#pragma unroll
        for (int b = 0; b < 6; b++) acc[a][b] = 0ull;

#pragma unroll 8
    for (int k = 0; k < 64; k++) {
        float4 h4 = *(const float4*)(sH + k * 128 + colb);
        const ulonglong2* wp = (const ulonglong2*)(sU + k * 48 + ob);
        ulonglong2 wa = wp[0], wb = wp[1], wc = wp[2];
        float hs[4] = { h4.x, h4.y, h4.z, h4.w };
#pragma unroll
        for (int ei = 0; ei < 4; ei++) {
            U64 xx = pack2(hs[ei], hs[ei]);
            fma2(acc[ei][0], wa.x, xx); fma2(acc[ei][1], wa.y, xx);
            fma2(acc[ei][2], wb.x, xx); fma2(acc[ei][3], wb.y, xx);
            fma2(acc[ei][4], wc.x, xx); fma2(acc[ei][5], wc.y, xx);
        }
    }
    __syncthreads();

    float* sOUT = sH;
#pragma unroll
    for (int op = 0; op < 6; op++) {
        float2 f[4];
#pragma unroll
        for (int ei = 0; ei < 4; ei++) f[ei] = unpk2(acc[ei][op]);
        int r0 = ob + 2 * op, r1 = ob + 2 * op + 1;
        *(float4*)(sOUT + SWIZ(r0, colb)) =
            make_float4(f[0].x * INV8, f[1].x * INV8, f[2].x * INV8, f[3].x * INV8);
        *(float4*)(sOUT + SWIZ(r1, colb)) =
            make_float4(f[0].y * INV8, f[1].y * INV8, f[2].y * INV8, f[3].y * INV8);
    }
    __syncthreads();

#pragma unroll
    for (int p = 0; p < 4; p++) {
        int q = 8 * p + g;
        int eQ = blockBase + 32 * warp + q;
        int sE  = __shfl_sync(0xffffffffu, srcIdx, q);
        int dE  = __shfl_sync(0xffffffffu, dstIdx, q);
        float eax = __shfl_sync(0xffffffffu, ea.x, q);
        float eay = __shfl_sync(0xffffffffu, ea.y, q);
        float eaz = __shfl_sync(0xffffffffu, ea.z, q);
        float eaw = __shfl_sync(0xffffffffu, ea.w, q);
        if (eQ < E) {
            int col = 32 * warp + q;
            float* m2 = g_mid2 + (size_t)dE * 48;
            const float4* gp = (const float4*)(g_h0 + (size_t)sE * 32 + 8 * j);
            float4 a0 = gp[0], a1 = gp[1];
            float w0 = sOUT[SWIZ(8 * j + 0, col)];
            float w1 = sOUT[SWIZ(8 * j + 1, col)];
            float w2 = sOUT[SWIZ(8 * j + 2, col)];
            float w3 = sOUT[SWIZ(8 * j + 3, col)];
            float w4 = sOUT[SWIZ(8 * j + 4, col)];
            float w5 = sOUT[SWIZ(8 * j + 5, col)];
            float w6 = sOUT[SWIZ(8 * j + 6, col)];
            float w7 = sOUT[SWIZ(8 * j + 7, col)];
            red4(m2 + 8 * j,     a0.x * eax * w0, a0.y * eax * w1,
                                 a0.z * eax * w2, a0.w * eax * w3);
            red4(m2 + 8 * j + 4, a1.x * eax * w4, a1.y * eax * w5,
                                 a1.z * eax * w6, a1.w * eax * w7);
            const float4* vp = (const float4*)(g_hv + (size_t)sE * 48 + 12 * j);
            float4 b0 = vp[0], b1 = vp[1], b2 = vp[2];
            float wv0 = sOUT[SWIZ(32 + 4 * j + 0, col)];
            float wv1 = sOUT[SWIZ(32 + 4 * j + 1, col)];
            float wv2 = sOUT[SWIZ(32 + 4 * j + 2, col)];
            float wv3 = sOUT[SWIZ(32 + 4 * j + 3, col)];
            float dv0 = (b0.x * eay + b0.y * eaz + b0.z * eaw) * INV_SQRT3 * wv0;
            float dv1 = (b0.w * eay + b1.x * eaz + b1.y * eaw) * INV_SQRT3 * wv1;
            float dv2 = (b1.z * eay + b1.w * eaz + b2.x * eaw) * INV_SQRT3 * wv2;
            float dv3 = (b2.y * eay + b2.z * eaz + b2.w * eaw) * INV_SQRT3 * wv3;
            red4(m2 + 32 + 4 * j, dv0, dv1, dv2, dv3);
        }
    }
}

// ---------------------------------------------------------------------------
// Kernel E: final node readout (staged mid2 reads)
// ---------------------------------------------------------------------------
__global__ __launch_bounds__(128)
void k_node3(const float* __restrict__ na, const float* __restrict__ Wl22,
             float* __restrict__ out, int N)
{
    __shared__ float sw[48];
    __shared__ float sbuf[128 * 49];
    for (int i = threadIdx.x; i < 48; i += 128) sw[i] = Wl22[i];

    int t = threadIdx.x;
    int blockBase = blockIdx.x * 128;
    int n = blockBase + t;
    int nv = N - blockBase; if (nv > 128) nv = 128;

    // coalesced read of mid2 slab into padded smem
    for (int i = t; i < nv * 48; i += 128)
        sbuf[(i / 48) * 49 + (i % 48)] = g_mid2[(size_t)blockBase * 48 + i];
    __syncthreads();

    if (t < nv) {
        float acc = 0.f;
        const float* row = sbuf + t * 49;
#pragma unroll
        for (int i = 0; i < 48; i++) acc += row[i] * sw[i];
        float x = acc * INV4 * INV_SQRT48 * na[n];
        out[n] = C_S * g_s2[n] + C_X * x;
    }
}

// ---------------------------------------------------------------------------
// Launch
// ---------------------------------------------------------------------------
extern "C" void kernel_launch(void* const* d_in, const int* in_sizes, int n_in,
                              void* d_out, int out_size)
{
    const float* node_input = (const float*)d_in[0];
    const float* node_attr  = (const float*)d_in[1];
    const float* edge_attr  = (const float*)d_in[2];
    const float* elen       = (const float*)d_in[3];
    const float* W_sc1      = (const float*)d_in[4];
    const float* W_lin1_1   = (const float*)d_in[5];
    const float* fc1_W1     = (const float*)d_in[6];
    const float* fc1_W2     = (const float*)d_in[7];
    const float* W_l2s_1    = (const float*)d_in[8];
    const float* W_l2v_1    = (const float*)d_in[9];
    const float* W_sc2      = (const float*)d_in[10];
    const float* W_lin1_2s  = (const float*)d_in[11];
    const float* W_lin1_2v  = (const float*)d_in[12];
    const float* fc2_W1     = (const float*)d_in[13];
    const float* fc2_W2     = (const float*)d_in[14];
    const float* W_lin2_2   = (const float*)d_in[15];
    const int*   esrc       = (const int*)d_in[16];
    const int*   edst       = (const int*)d_in[17];
    float* out = (float*)d_out;

    int N = in_sizes[1];
    int E = in_sizes[16];
    int eblocks = (E + EPB - 1) / EPB;

    k_node1<<<(N + 127) / 128, 128>>>(node_input, node_attr, W_sc1, W_lin1_1, N);
    k_edge1<<<eblocks, 128>>>(elen, edge_attr, esrc, edst, fc1_W1, fc1_W2, E);
    k_node2<<<(N + 127) / 128, 128>>>(node_attr, W_l2s_1, W_l2v_1, W_sc2,
                                      W_lin1_2s, W_lin1_2v, N);
    k_edge2<<<eblocks, 128>>>(elen, edge_attr, esrc, edst, fc2_W1, fc2_W2, E);
    k_node3<<<(N + 127) / 128, 128>>>(node_attr, W_lin2_2, out, N);
}

// round 16
// speedup vs baseline: 1.0576x; 1.0007x over previous
#include <cuda_runtime.h>

#define EPB 128

#define INV4        0.25f
#define INV_SQRT10  0.3162277660168379f
#define INV8        0.125f
#define INV_SQRT32  0.1767766952966369f
#define INV_SQRT48  0.1443375672974064f
#define INV_SQRT3   0.5773502691896258f
#define C_S         0.3826834323650898f
#define C_X         0.9238795325112867f

#define N_NODES_MAX 100000
#define SOS 132   // sOUT padded stride

// XOR swizzle for sOUT column reads (R8, proven)
#define SWX(r)      (8 * (((r) >> 3) & 3))
#define SWIZ(r, c)  ((r) * SOS + ((c) ^ SWX(r)))

typedef unsigned long long U64;

// ---------------------------------------------------------------------------
// Scratch
// ---------------------------------------------------------------------------
__device__ __align__(16) float g_x1  [(size_t)N_NODES_MAX * 16];
__device__ __align__(16) float g_mid [(size_t)N_NODES_MAX * 64];
__device__ __align__(16) float g_s2  [(size_t)N_NODES_MAX];
__device__ __align__(16) float g_h0  [(size_t)N_NODES_MAX * 32];
__device__ __align__(16) float g_hv  [(size_t)N_NODES_MAX * 48];
__device__ __align__(16) float g_mid2[(size_t)N_NODES_MAX * 48];

__device__ __forceinline__ float fast_sigmoid(float x) {
    return __fdividef(1.0f, 1.0f + __expf(-x));
}
__device__ __forceinline__ float fast_silu(float x) {
    return __fdividef(x, 1.0f + __expf(-x));
}

__device__ __forceinline__ U64 pack2(float a, float b) {
    U64 r; asm("mov.b64 %0, {%1, %2};" : "=l"(r) : "f"(a), "f"(b)); return r;
}
__device__ __forceinline__ float2 unpk2(U64 v) {
    float2 r; asm("mov.b64 {%0, %1}, %2;" : "=f"(r.x), "=f"(r.y) : "l"(v)); return r;
}
__device__ __forceinline__ void fma2(U64& d, U64 a, U64 b) {
    asm("fma.rn.f32x2 %0, %1, %2, %0;" : "+l"(d) : "l"(a), "l"(b));
}
__device__ __forceinline__ void mul2(U64& d, U64 a) {
    asm("mul.rn.f32x2 %0, %0, %1;" : "+l"(d) : "l"(a));
}
__device__ __forceinline__ void red4(float* addr, float a, float b, float c, float d) {
    asm volatile("red.global.add.v4.f32 [%0], {%1, %2, %3, %4};"
                 :: "l"(addr), "f"(a), "f"(b), "f"(c), "f"(d) : "memory");
}

// ---------------------------------------------------------------------------
// Kernel A: x1[N,16] only; zero mid & mid2 (coalesced)
// ---------------------------------------------------------------------------
__global__ __launch_bounds__(128)
void k_node1(const float* __restrict__ ni, const float* __restrict__ na,
             const float* __restrict__ Wl11, int N)
{
    __shared__ __align__(16) float sB[16 * 16];
    __shared__ float sbuf[128 * 17];
    for (int i = threadIdx.x; i < 16 * 16; i += 128) sB[i] = Wl11[i];
    __syncthreads();

    int t = threadIdx.x;
    int blockBase = blockIdx.x * 128;
    int n = blockBase + t;
    int nv = N - blockBase; if (nv > 128) nv = 128;
    bool valid = (t < nv);

    U64 xv2[8];
    float a = 0.f;
    if (valid) {
        float in[16];
        const float4* p = (const float4*)(ni + (size_t)n * 16);
#pragma unroll
        for (int i = 0; i < 4; i++) {
            float4 v = p[i];
            in[4 * i] = v.x; in[4 * i + 1] = v.y; in[4 * i + 2] = v.z; in[4 * i + 3] = v.w;
        }
        a = na[n];

#pragma unroll
        for (int j = 0; j < 8; j++) xv2[j] = 0ull;

#pragma unroll
        for (int k = 0; k < 16; k++) {
            U64 xx = pack2(in[k], in[k]);
            const ulonglong2* wb = (const ulonglong2*)(sB + k * 16);
#pragma unroll
            for (int j4 = 0; j4 < 4; j4++) {
                ulonglong2 w = wb[j4];
                fma2(xv2[2 * j4], w.x, xx);
                fma2(xv2[2 * j4 + 1], w.y, xx);
            }
        }
    }

    float sa = INV4 * a;
    if (valid) {
#pragma unroll
        for (int j = 0; j < 8; j++) {
            float2 f = unpk2(xv2[j]);
            sbuf[t * 17 + 2 * j]     = f.x * sa;
            sbuf[t * 17 + 2 * j + 1] = f.y * sa;
        }
    }
    __syncthreads();
    for (int i = t; i < nv * 16; i += 128)
        g_x1[(size_t)blockBase * 16 + i] = sbuf[(i / 16) * 17 + (i % 16)];

    for (int i = t; i < nv * 64; i += 128) g_mid [(size_t)blockBase * 64 + i] = 0.f;
    for (int i = t; i < nv * 48; i += 128) g_mid2[(size_t)blockBase * 48 + i] = 0.f;
}

// ---------------------------------------------------------------------------
// Kernel B: edge pass 1 (R12 exact — frozen)
// ---------------------------------------------------------------------------
__global__ __launch_bounds__(128, 5)
void k_edge1(const float* __restrict__ elen, const float* __restrict__ eattr,
             const int* __restrict__ esrc, const int* __restrict__ edst,
             const float* __restrict__ W1, const float* __restrict__ W2, int E)
{
    __shared__ __align__(16) float sU[2048];
    __shared__ __align__(16) float sH[64 * 128];

    float* sEL = sU + 640;

    int t = threadIdx.x;
    int warp = t >> 5, lane = t & 31;
    int colb = 4 * lane;
    int hb = warp * 16;
    int ob = warp * 8;
    int j = lane & 3;
    int g = lane >> 2;

    for (int i = t; i < 640; i += 128) sU[i] = W1[i];

    int blockBase = blockIdx.x * EPB;
    int e = blockBase + t;
    int eL = e < E ? e : E - 1;

    int srcIdx = esrc[eL];
    int dstIdx = edst[eL];
    float4 ea = ((const float4*)eattr)[eL];

    {
        const float2* ep = (const float2*)(elen + (size_t)eL * 10);
#pragma unroll
        for (int i = 0; i < 5; i++) {
            float2 v = ep[i];
            sEL[(2 * i) * 128 + t]     = v.x;
            sEL[(2 * i + 1) * 128 + t] = v.y;
        }
    }
    __syncthreads();

#pragma unroll
    for (int half = 0; half < 2; half++) {
        int hbh = hb + 8 * half;
        U64 hacc[4][4];
#pragma unroll
        for (int a = 0; a < 4; a++)
#pragma unroll
            for (int b = 0; b < 4; b++) hacc[a][b] = 0ull;

#pragma unroll
        for (int k = 0; k < 10; k++) {
            float4 x4 = *(const float4*)(sEL + k * 128 + colb);
            const ulonglong2* wp = (const ulonglong2*)(sU + k * 64 + hbh);
            ulonglong2 w0 = wp[0], w1 = wp[1];
            float xs4[4] = { x4.x, x4.y, x4.z, x4.w };
#pragma unroll
            for (int ei = 0; ei < 4; ei++) {
                U64 xx = pack2(xs4[ei], xs4[ei]);
                fma2(hacc[ei][0], w0.x, xx); fma2(hacc[ei][1], w0.y, xx);
                fma2(hacc[ei][2], w1.x, xx); fma2(hacc[ei][3], w1.y, xx);
            }
        }
#pragma unroll
        for (int jp = 0; jp < 4; jp++) {
            float2 f[4];
#pragma unroll
            for (int ei = 0; ei < 4; ei++) {
                f[ei] = unpk2(hacc[ei][jp]);
                f[ei].x = fast_silu(f[ei].x * INV_SQRT10);
                f[ei].y = fast_silu(f[ei].y * INV_SQRT10);
            }
            *(float4*)(sH + (hbh + 2 * jp) * 128 + colb) =
                make_float4(f[0].x, f[1].x, f[2].x, f[3].x);
            *(float4*)(sH + (hbh + 2 * jp + 1) * 128 + colb) =
                make_float4(f[0].y, f[1].y, f[2].y, f[3].y);
        }
    }
    __syncthreads();

    for (int i = t; i < 2048; i += 128) sU[i] = W2[i];
    __syncthreads();

    U64 acc[4][4];
#pragma unroll
    for (int a = 0; a < 4; a++)
#pragma unroll
        for (int b = 0; b < 4; b++) acc[a][b] = 0ull;

#pragma unroll 8
    for (int k = 0; k < 64; k++) {
        float4 h4 = *(const float4*)(sH + k * 128 + colb);
        const ulonglong2* wp = (const ulonglong2*)(sU + k * 32 + ob);
        ulonglong2 wa = wp[0], wb = wp[1];
        float hs[4] = { h4.x, h4.y, h4.z, h4.w };
#pragma unroll
        for (int ei = 0; ei < 4; ei++) {
            U64 xx = pack2(hs[ei], hs[ei]);
            fma2(acc[ei][0], wa.x, xx); fma2(acc[ei][1], wa.y, xx);
            fma2(acc[ei][2], wb.x, xx); fma2(acc[ei][3], wb.y, xx);
        }
    }
    __syncthreads();

    float* sOUT = sH;
#pragma unroll
    for (int op = 0; op < 4; op++) {
        float2 f[4];
#pragma unroll
        for (int ei = 0; ei < 4; ei++) f[ei] = unpk2(acc[ei][op]);
        int r0 = ob + 2 * op, r1 = ob + 2 * op + 1;
        *(float4*)(sOUT + SWIZ(r0, colb)) =
            make_float4(f[0].x * INV8, f[1].x * INV8, f[2].x * INV8, f[3].x * INV8);
        *(float4*)(sOUT + SWIZ(r1, colb)) =
            make_float4(f[0].y * INV8, f[1].y * INV8, f[2].y * INV8, f[3].y * INV8);
    }
    __syncthreads();

#pragma unroll
    for (int p = 0; p < 4; p++) {
        int q = 8 * p + g;
        int eQ = blockBase + 32 * warp + q;
        int sE  = __shfl_sync(0xffffffffu, srcIdx, q);
        int dE  = __shfl_sync(0xffffffffu, dstIdx, q);
        float eax = __shfl_sync(0xffffffffu, ea.x, q);
        float eay = __shfl_sync(0xffffffffu, ea.y, q);
        float eaz = __shfl_sync(0xffffffffu, ea.z, q);
        float eaw = __shfl_sync(0xffffffffu, ea.w, q);
        if (eQ < E) {
            int col = 32 * warp + q;
            float4 x = *(const float4*)(g_x1 + (size_t)sE * 16 + 4 * j);
            float* mrow = g_mid + (size_t)dE * 64;
            float w0 = sOUT[SWIZ(4 * j + 0, col)];
            float w1 = sOUT[SWIZ(4 * j + 1, col)];
            float w2 = sOUT[SWIZ(4 * j + 2, col)];
            float w3 = sOUT[SWIZ(4 * j + 3, col)];
            red4(mrow + 4 * j, x.x * eax * w0, x.y * eax * w1,
                               x.z * eax * w2, x.w * eax * w3);
            float t0 = x.x * sOUT[SWIZ(16 + 4 * j + 0, col)];
            float t1 = x.y * sOUT[SWIZ(16 + 4 * j + 1, col)];
            float t2 = x.z * sOUT[SWIZ(16 + 4 * j + 2, col)];
            float t3 = x.w * sOUT[SWIZ(16 + 4 * j + 3, col)];
            float* f1p = mrow + 16 + 12 * j;
            red4(f1p + 0, t0 * eay, t0 * eaz, t0 * eaw, t1 * eay);
            red4(f1p + 4, t1 * eaz, t1 * eaw, t2 * eay, t2 * eaz);
            red4(f1p + 8, t2 * eaw, t3 * eay, t3 * eaz, t3 * eaw);
        }
    }
}

// ---------------------------------------------------------------------------
// Kernel C: per-node mid processing; sscal fused in; staged mid reads;
// coalesced h0/hv stores
// ---------------------------------------------------------------------------
__global__ __launch_bounds__(128)
void k_node2(const float* __restrict__ ni, const float* __restrict__ na,
             const float* __restrict__ Wsc1,
             const float* __restrict__ Wl2s, const float* __restrict__ Wl2v,
             const float* __restrict__ Wsc2, const float* __restrict__ W12s,
             const float* __restrict__ W12v, int N)
{
    __shared__ __align__(16) float sA[16 * 48];
    __shared__ __align__(16) float sL2S[16 * 48];
    __shared__ __align__(16) float sL2V[16 * 16];
    __shared__ float sSC2[32];
    __shared__ __align__(16) float s12S[32 * 32];
    __shared__ __align__(16) float s12V[16 * 16];
    __shared__ float sbuf[128 * 65];
    for (int i = threadIdx.x; i < 16 * 48; i += 128) sA[i] = Wsc1[i];
    for (int i = threadIdx.x; i < 16 * 48; i += 128) sL2S[i] = Wl2s[i];
    for (int i = threadIdx.x; i < 16 * 16; i += 128) sL2V[i] = Wl2v[i];
    for (int i = threadIdx.x; i < 32;      i += 128) sSC2[i] = Wsc2[i];
    for (int i = threadIdx.x; i < 32 * 32; i += 128) s12S[i] = W12s[i];
    for (int i = threadIdx.x; i < 16 * 16; i += 128) s12V[i] = W12v[i];

    int t = threadIdx.x;
    int blockBase = blockIdx.x * 128;
    int n = blockBase + t;
    int nv = N - blockBase; if (nv > 128) nv = 128;
    bool valid = (t < nv);

    // stage node_input slab (coalesced), stride 17
    for (int i = t; i < nv * 16; i += 128)
        sbuf[(i / 16) * 17 + (i % 16)] = ni[(size_t)blockBase * 16 + i];
    __syncthreads();

    float a = 0.f, s = 0.f;
    U64 sc2[24];
    if (valid) {
        a = na[n];
        s = INV4 * a;
        float in[16];
        const float* r = sbuf + t * 17;
#pragma unroll
        for (int i = 0; i < 16; i++) in[i] = r[i];
#pragma unroll
        for (int c = 0; c < 24; c++) sc2[c] = 0ull;
#pragma unroll
        for (int k = 0; k < 16; k++) {
            U64 xx = pack2(in[k], in[k]);
            const ulonglong2* wa = (const ulonglong2*)(sA + k * 48);
#pragma unroll
            for (int c4 = 0; c4 < 12; c4++) {
                ulonglong2 w = wa[c4];
                fma2(sc2[2 * c4], w.x, xx);
                fma2(sc2[2 * c4 + 1], w.y, xx);
            }
        }
    }
    __syncthreads();

    // stage mid slab (coalesced), stride 65
    for (int i = t; i < nv * 64; i += 128)
        sbuf[(i / 64) * 65 + (i % 64)] = g_mid[(size_t)blockBase * 64 + i];
    __syncthreads();

    U64 h02[16];
    float gs[16];
    if (valid) {
        const float* mrow = sbuf + t * 65;
        float m0[16];
#pragma unroll
        for (int i = 0; i < 16; i++) m0[i] = mrow[i] * INV4;

        U64 ys2[24];
#pragma unroll
        for (int c = 0; c < 24; c++) ys2[c] = 0ull;
#pragma unroll
        for (int u = 0; u < 16; u++) {
            U64 xx = pack2(m0[u], m0[u]);
            const ulonglong2* wr = (const ulonglong2*)(sL2S + u * 48);
#pragma unroll
            for (int c4 = 0; c4 < 12; c4++) {
                ulonglong2 w = wr[c4];
                fma2(ys2[2 * c4], w.x, xx);
                fma2(ys2[2 * c4 + 1], w.y, xx);
            }
        }

        float sa = INV4 * a;   // sscal scale (same as original kernel A)
        float scal[32];
#pragma unroll
        for (int i = 0; i < 8; i++) {
            float2 sc0 = unpk2(sc2[2 * i]);
            float2 sc1 = unpk2(sc2[2 * i + 1]);
            float2 y0 = unpk2(ys2[2 * i]);
            float2 y1 = unpk2(ys2[2 * i + 1]);
            scal[4 * i + 0] = fast_silu(C_S * (sc0.x * sa) + C_X * (y0.x * s));
            scal[4 * i + 1] = fast_silu(C_S * (sc0.y * sa) + C_X * (y0.y * s));
            scal[4 * i + 2] = fast_silu(C_S * (sc1.x * sa) + C_X * (y1.x * s));
            scal[4 * i + 3] = fast_silu(C_S * (sc1.y * sa) + C_X * (y1.y * s));
        }
#pragma unroll
        for (int i = 0; i < 4; i++) {
            float2 sc0 = unpk2(sc2[16 + 2 * i]);
            float2 sc1 = unpk2(sc2[16 + 2 * i + 1]);
            float2 y0 = unpk2(ys2[16 + 2 * i]);
            float2 y1 = unpk2(ys2[16 + 2 * i + 1]);
            gs[4 * i + 0] = fast_sigmoid(C_S * (sc0.x * sa) + C_X * (y0.x * s)) * s;
            gs[4 * i + 1] = fast_sigmoid(C_S * (sc0.y * sa) + C_X * (y0.y * s)) * s;
            gs[4 * i + 2] = fast_sigmoid(C_S * (sc1.x * sa) + C_X * (y1.x * s)) * s;
            gs[4 * i + 3] = fast_sigmoid(C_S * (sc1.y * sa) + C_X * (y1.y * s)) * s;
        }

        float s2v = 0.f;
#pragma unroll
        for (int o = 0; o < 32; o++) s2v += scal[o] * sSC2[o];
        g_s2[n] = s2v * INV_SQRT32 * a;

#pragma unroll
        for (int p = 0; p < 16; p++) h02[p] = 0ull;
#pragma unroll
        for (int o = 0; o < 32; o++) {
            U64 xx = pack2(scal[o], scal[o]);
            const ulonglong2* wr = (const ulonglong2*)(s12S + o * 32);
#pragma unroll
            for (int p4 = 0; p4 < 8; p4++) {
                ulonglong2 w = wr[p4];
                fma2(h02[2 * p4], w.x, xx);
                fma2(h02[2 * p4 + 1], w.y, xx);
            }
        }
    }

    // yv / hv (m1 read from staged slab)
    U64 hv0[8], hv1[8], hv2[8];
    if (valid) {
        const float* mrow = sbuf + t * 65;
        float m1[48];
#pragma unroll
        for (int i = 0; i < 48; i++) m1[i] = mrow[16 + i] * INV4;

        U64 yv0[8], yv1[8], yv2[8];
#pragma unroll
        for (int q = 0; q < 8; q++) { yv0[q] = 0ull; yv1[q] = 0ull; yv2[q] = 0ull; }
#pragma unroll
        for (int u = 0; u < 16; u++) {
            U64 p0 = pack2(m1[3 * u + 0], m1[3 * u + 0]);
            U64 p1 = pack2(m1[3 * u + 1], m1[3 * u + 1]);
            U64 p2 = pack2(m1[3 * u + 2], m1[3 * u + 2]);
            const U64* wr = (const U64*)(sL2V + u * 16);
#pragma unroll
            for (int q = 0; q < 8; q++) {
                U64 w = wr[q];
                fma2(yv0[q], w, p0);
                fma2(yv1[q], w, p1);
                fma2(yv2[q], w, p2);
            }
        }
#pragma unroll
        for (int q = 0; q < 8; q++) {
            U64 gp = pack2(gs[2 * q], gs[2 * q + 1]);
            mul2(yv0[q], gp);
            mul2(yv1[q], gp);
            mul2(yv2[q], gp);
        }

#pragma unroll
        for (int q = 0; q < 8; q++) { hv0[q] = 0ull; hv1[q] = 0ull; hv2[q] = 0ull; }
#pragma unroll
        for (int qw = 0; qw < 8; qw++) {
            float2 v0 = unpk2(yv0[qw]);
            float2 v1 = unpk2(yv1[qw]);
            float2 v2 = unpk2(yv2[qw]);
            {
                U64 p0 = pack2(v0.x, v0.x), p1 = pack2(v1.x, v1.x), p2 = pack2(v2.x, v2.x);
                const U64* wr = (const U64*)(s12V + (2 * qw) * 16);
#pragma unroll
                for (int q = 0; q < 8; q++) {
                    U64 w = wr[q];
                    fma2(hv0[q], w, p0);
                    fma2(hv1[q], w, p1);
                    fma2(hv2[q], w, p2);
                }
            }
            {
                U64 p0 = pack2(v0.y, v0.y), p1 = pack2(v1.y, v1.y), p2 = pack2(v2.y, v2.y);
                const U64* wr = (const U64*)(s12V + (2 * qw + 1) * 16);
#pragma unroll
                for (int q = 0; q < 8; q++) {
                    U64 w = wr[q];
                    fma2(hv0[q], w, p0);
                    fma2(hv1[q], w, p1);
                    fma2(hv2[q], w, p2);
                }
            }
        }
    }
    __syncthreads();   // done reading mid slab

    // stage h0 -> coalesced store
    if (valid) {
        float sh = INV_SQRT32 * a;
#pragma unroll
        for (int p = 0; p < 16; p++) {
            float2 f = unpk2(h02[p]);
            sbuf[t * 33 + 2 * p]     = f.x * sh;
            sbuf[t * 33 + 2 * p + 1] = f.y * sh;
        }
    }
    __syncthreads();
    for (int i = t; i < nv * 32; i += 128)
        g_h0[(size_t)blockBase * 32 + i] = sbuf[(i / 32) * 33 + (i % 32)];
    __syncthreads();

    // stage hv -> coalesced store
    if (valid) {
#pragma unroll
        for (int q = 0; q < 8; q++) {
            float2 f0 = unpk2(hv0[q]);
            float2 f1 = unpk2(hv1[q]);
            float2 f2 = unpk2(hv2[q]);
            sbuf[t * 49 + 6 * q + 0] = f0.x * s;
            sbuf[t * 49 + 6 * q + 1] = f1.x * s;
            sbuf[t * 49 + 6 * q + 2] = f2.x * s;
            sbuf[t * 49 + 6 * q + 3] = f0.y * s;
            sbuf[t * 49 + 6 * q + 4] = f1.y * s;
            sbuf[t * 49 + 6 * q + 5] = f2.y * s;
        }
    }
    __syncthreads();
    for (int i = t; i < nv * 48; i += 128)
        g_hv[(size_t)blockBase * 48 + i] = sbuf[(i / 48) * 49 + (i % 48)];
}

// ---------------------------------------------------------------------------
// Kernel D: edge pass 2 (R12 exact — frozen)
// ---------------------------------------------------------------------------
__global__ __launch_bounds__(128, 5)
void k_edge2(const float* __restrict__ elen, const float* __restrict__ eattr,
             const int* __restrict__ esrc, const int* __restrict__ edst,
             const float* __restrict__ W1, const float* __restrict__ W2, int E)
{
    __shared__ __align__(16) float sU[3072];
    __shared__ __align__(16) float sH[64 * 128];

    float* sEL = sU + 640;

    int t = threadIdx.x;
    int warp = t >> 5, lane = t & 31;
    int colb = 4 * lane;
    int hb = warp * 16;
    int ob = warp * 12;
    int j = lane & 3;
    int g = lane >> 2;

    for (int i = t; i < 640; i += 128) sU[i] = W1[i];

    int blockBase = blockIdx.x * EPB;
    int e = blockBase + t;
    int eL = e < E ? e : E - 1;

    int srcIdx = esrc[eL];
    int dstIdx = edst[eL];
    float4 ea = ((const float4*)eattr)[eL];

    {
        const float2* ep = (const float2*)(elen + (size_t)eL * 10);
#pragma unroll
        for (int i = 0; i < 5; i++) {
            float2 v = ep[i];
            sEL[(2 * i) * 128 + t]     = v.x;
            sEL[(2 * i + 1) * 128 + t] = v.y;
        }
    }
    __syncthreads();

#pragma unroll
    for (int half = 0; half < 2; half++) {
        int hbh = hb + 8 * half;
        U64 hacc[4][4];
#pragma unroll
        for (int a = 0; a < 4; a++)
#pragma unroll
            for (int b = 0; b < 4; b++) hacc[a][b] = 0ull;

#pragma unroll
        for (int k = 0; k < 10; k++) {
            float4 x4 = *(const float4*)(sEL + k * 128 + colb);
            const ulonglong2* wp = (const ulonglong2*)(sU + k * 64 + hbh);
            ulonglong2 w0 = wp[0], w1 = wp[1];
            float xs4[4] = { x4.x, x4.y, x4.z, x4.w };
#pragma unroll
            for (int ei = 0; ei < 4; ei++) {
                U64 xx = pack2(xs4[ei], xs4[ei]);
                fma2(hacc[ei][0], w0.x, xx); fma2(hacc[ei][1], w0.y, xx);
                fma2(hacc[ei][2], w1.x, xx); fma2(hacc[ei][3], w1.y, xx);
            }
        }
#pragma unroll
        for (int jp = 0; jp < 4; jp++) {
            float2 f[4];
#pragma unroll
            for (int ei = 0; ei < 4; ei++) {
                f[ei] = unpk2(hacc[ei][jp]);
                f[ei].x = fast_silu(f[ei].x * INV_SQRT10);
                f[ei].y = fast_silu(f[ei].y * INV_SQRT10);
            }
            *(float4*)(sH + (hbh + 2 * jp) * 128 + colb) =
                make_float4(f[0].x, f[1].x, f[2].x, f[3].x);
            *(float4*)(sH + (hbh + 2 * jp + 1) * 128 + colb) =
                make_float4(f[0].y, f[1].y, f[2].y, f[3].y);
        }
    }
    __syncthreads();

    for (int i = t; i < 3072; i += 128) sU[i] = W2[i];
    __syncthreads();

    U64 acc[4][6];
#pragma unroll
    for (int a = 0; a < 4; a++)
#pragma unroll
        for (int b = 0; b < 6; b++) acc[a][b] = 0ull;

#pragma unroll 8
    for (int k = 0; k < 64; k++) {
        float4 h4 = *(const float4*)(sH + k * 128 + colb);
        const ulonglong2* wp = (const ulonglong2*)(sU + k * 48 + ob);
        ulonglong2 wa = wp[0], wb = wp[1], wc = wp[2];
        float hs[4] = { h4.x, h4.y, h4.z, h4.w };
#pragma unroll
        for (int ei = 0; ei < 4; ei++) {
            U64 xx = pack2(hs[ei], hs[ei]);
            fma2(acc[ei][0], wa.x, xx); fma2(acc[ei][1], wa.y, xx);
            fma2(acc[ei][2], wb.x, xx); fma2(acc[ei][3], wb.y, xx);
            fma2(acc[ei][4], wc.x, xx); fma2(acc[ei][5], wc.y, xx);
        }
    }
    __syncthreads();

    float* sOUT = sH;
#pragma unroll
    for (int op = 0; op < 6; op++) {
        float2 f[4];
#pragma unroll
        for (int ei = 0; ei < 4; ei++) f[ei] = unpk2(acc[ei][op]);
        int r0 = ob + 2 * op, r1 = ob + 2 * op + 1;
        *(float4*)(sOUT + SWIZ(r0, colb)) =
            make_float4(f[0].x * INV8, f[1].x * INV8, f[2].x * INV8, f[3].x * INV8);
        *(float4*)(sOUT + SWIZ(r1, colb)) =
            make_float4(f[0].y * INV8, f[1].y * INV8, f[2].y * INV8, f[3].y * INV8);
    }
    __syncthreads();

#pragma unroll
    for (int p = 0; p < 4; p++) {
        int q = 8 * p + g;
        int eQ = blockBase + 32 * warp + q;
        int sE  = __shfl_sync(0xffffffffu, srcIdx, q);
        int dE  = __shfl_sync(0xffffffffu, dstIdx, q);
        float eax = __shfl_sync(0xffffffffu, ea.x, q);
        float eay = __shfl_sync(0xffffffffu, ea.y, q);
        float eaz = __shfl_sync(0xffffffffu, ea.z, q);
        float eaw = __shfl_sync(0xffffffffu, ea.w, q);
        if (eQ < E) {
            int col = 32 * warp + q;
            float* m2 = g_mid2 + (size_t)dE * 48;
            const float4* gp = (const float4*)(g_h0 + (size_t)sE * 32 + 8 * j);
            float4 a0 = gp[0], a1 = gp[1];
            float w0 = sOUT[SWIZ(8 * j + 0, col)];
            float w1 = sOUT[SWIZ(8 * j + 1, col)];
            float w2 = sOUT[SWIZ(8 * j + 2, col)];
            float w3 = sOUT[SWIZ(8 * j + 3, col)];
            float w4 = sOUT[SWIZ(8 * j + 4, col)];
            float w5 = sOUT[SWIZ(8 * j + 5, col)];
            float w6 = sOUT[SWIZ(8 * j + 6, col)];
            float w7 = sOUT[SWIZ(8 * j + 7, col)];
            red4(m2 + 8 * j,     a0.x * eax * w0, a0.y * eax * w1,
                                 a0.z * eax * w2, a0.w * eax * w3);
            red4(m2 + 8 * j + 4, a1.x * eax * w4, a1.y * eax * w5,
                                 a1.z * eax * w6, a1.w * eax * w7);
            const float4* vp = (const float4*)(g_hv + (size_t)sE * 48 + 12 * j);
            float4 b0 = vp[0], b1 = vp[1], b2 = vp[2];
            float wv0 = sOUT[SWIZ(32 + 4 * j + 0, col)];
            float wv1 = sOUT[SWIZ(32 + 4 * j + 1, col)];
            float wv2 = sOUT[SWIZ(32 + 4 * j + 2, col)];
            float wv3 = sOUT[SWIZ(32 + 4 * j + 3, col)];
            float dv0 = (b0.x * eay + b0.y * eaz + b0.z * eaw) * INV_SQRT3 * wv0;
            float dv1 = (b0.w * eay + b1.x * eaz + b1.y * eaw) * INV_SQRT3 * wv1;
            float dv2 = (b1.z * eay + b1.w * eaz + b2.x * eaw) * INV_SQRT3 * wv2;
            float dv3 = (b2.y * eay + b2.z * eaz + b2.w * eaw) * INV_SQRT3 * wv3;
            red4(m2 + 32 + 4 * j, dv0, dv1, dv2, dv3);
        }
    }
}

// ---------------------------------------------------------------------------
// Kernel E: final node readout (staged mid2 reads)
// ---------------------------------------------------------------------------
__global__ __launch_bounds__(128)
void k_node3(const float* __restrict__ na, const float* __restrict__ Wl22,
             float* __restrict__ out, int N)
{
    __shared__ float sw[48];
    __shared__ float sbuf[128 * 49];
    for (int i = threadIdx.x; i < 48; i += 128) sw[i] = Wl22[i];

    int t = threadIdx.x;
    int blockBase = blockIdx.x * 128;
    int n = blockBase + t;
    int nv = N - blockBase; if (nv > 128) nv = 128;

    for (int i = t; i < nv * 48; i += 128)
        sbuf[(i / 48) * 49 + (i % 48)] = g_mid2[(size_t)blockBase * 48 + i];
    __syncthreads();

    if (t < nv) {
        float acc = 0.f;
        const float* row = sbuf + t * 49;
#pragma unroll
        for (int i = 0; i < 48; i++) acc += row[i] * sw[i];
        float x = acc * INV4 * INV_SQRT48 * na[n];
        out[n] = C_S * g_s2[n] + C_X * x;
    }
}

// ---------------------------------------------------------------------------
// Launch
// ---------------------------------------------------------------------------
extern "C" void kernel_launch(void* const* d_in, const int* in_sizes, int n_in,
                              void* d_out, int out_size)
{
    const float* node_input = (const float*)d_in[0];
    const float* node_attr  = (const float*)d_in[1];
    const float* edge_attr  = (const float*)d_in[2];
    const float* elen       = (const float*)d_in[3];
    const float* W_sc1      = (const float*)d_in[4];
    const float* W_lin1_1   = (const float*)d_in[5];
    const float* fc1_W1     = (const float*)d_in[6];
    const float* fc1_W2     = (const float*)d_in[7];
    const float* W_l2s_1    = (const float*)d_in[8];
    const float* W_l2v_1    = (const float*)d_in[9];
    const float* W_sc2      = (const float*)d_in[10];
    const float* W_lin1_2s  = (const float*)d_in[11];
    const float* W_lin1_2v  = (const float*)d_in[12];
    const float* fc2_W1     = (const float*)d_in[13];
    const float* fc2_W2     = (const float*)d_in[14];
    const float* W_lin2_2   = (const float*)d_in[15];
    const int*   esrc       = (const int*)d_in[16];
    const int*   edst       = (const int*)d_in[17];
    float* out = (float*)d_out;

    int N = in_sizes[1];
    int E = in_sizes[16];
    int eblocks = (E + EPB - 1) / EPB;

    k_node1<<<(N + 127) / 128, 128>>>(node_input, node_attr, W_lin1_1, N);
    k_edge1<<<eblocks, 128>>>(elen, edge_attr, esrc, edst, fc1_W1, fc1_W2, E);
    k_node2<<<(N + 127) / 128, 128>>>(node_input, node_attr, W_sc1,
                                      W_l2s_1, W_l2v_1, W_sc2,
                                      W_lin1_2s, W_lin1_2v, N);
    k_edge2<<<eblocks, 128>>>(elen, edge_attr, esrc, edst, fc2_W1, fc2_W2, E);
    k_node3<<<(N + 127) / 128, 128>>>(node_attr, W_lin2_2, out, N);
}